// round 1
// baseline (speedup 1.0000x reference)
#include <cuda_runtime.h>
#include <cstdint>

// Problem dims
#define NIN   128
#define NHID  256
#define NDEC  512
#define NOUT  10
#define BATCH 32
#define NSET  4096

// Encoder tiling
#define TM        64                    // rows per CTA
#define NTHREADS  256                   // 8 warps
#define ASTRIDE   260                   // padded float stride, activation buffers (bank-conflict free A-frag LDS)
#define WSTRIDE   264                   // padded float stride, staged W rows (bank-conflict free B-frag LDS)
#define NTILES_ENC (BATCH * NSET / TM)  // 2048 CTAs

// Deterministic scratch for per-tile column sums (fully overwritten every launch)
__device__ float g_partial[NTILES_ENC * NHID];

// ---------------------------------------------------------------------------
// helpers
// ---------------------------------------------------------------------------
__device__ __forceinline__ uint32_t f2tf32(float f) {
    uint32_t u;
    asm("cvt.rna.tf32.f32 %0, %1;" : "=r"(u) : "f"(f));
    return u;
}
__device__ __forceinline__ float tf32r(float f) {       // round fp32 -> tf32 value (kept in fp32 container)
    return __uint_as_float(f2tf32(f));
}

// m16n8k8 tf32 MMA, row.col, fp32 accumulate (D == C)
__device__ __forceinline__ void mma8(float c[4], const uint32_t a[4], uint32_t b0, uint32_t b1) {
    asm volatile(
        "mma.sync.aligned.m16n8k8.row.col.f32.tf32.tf32.f32 "
        "{%0,%1,%2,%3},{%4,%5,%6,%7},{%8,%9},{%0,%1,%2,%3};\n"
        : "+f"(c[0]), "+f"(c[1]), "+f"(c[2]), "+f"(c[3])
        : "r"(a[0]), "r"(a[1]), "r"(a[2]), "r"(a[3]), "r"(b0), "r"(b1));
}

// Load one 8-row k-slice of W (8 x 256 fp32 = 2048 floats) into registers (coalesced)
__device__ __forceinline__ void stage_load(const float* __restrict__ W, int kk, float4 v[2], int tid) {
    const float4* p = reinterpret_cast<const float4*>(W + kk * NHID);
    v[0] = p[tid];
    v[1] = p[tid + 256];
}

// Split into tf32 hi/lo and store to the staged smem slice
__device__ __forceinline__ void stage_store(const float4 v[2], float* whi, float* wlo, int tid) {
#pragma unroll
    for (int i = 0; i < 2; i++) {
        int lin = (tid + 256 * i) * 4;
        int k   = lin >> 8;       // / 256 (row of the 8xNHID slice)
        int cc  = lin & 255;      // col
        float* ph = whi + k * WSTRIDE + cc;
        float* pl = wlo + k * WSTRIDE + cc;
        float xs[4] = {v[i].x, v[i].y, v[i].z, v[i].w};
#pragma unroll
        for (int j = 0; j < 4; j++) {
            float h = tf32r(xs[j]);
            float l = tf32r(xs[j] - h);   // residual, also tf32-rounded
            ph[j] = h;
            pl[j] = l;
        }
    }
}

// ---------------------------------------------------------------------------
// one fused linear+bias+relu layer: out[64 x 256] = relu(in[64 x K] @ W[K x 256] + b)
// Activations are tf32-rounded fp32 in smem. Weights get hi/lo tf32 split (2 MMAs).
// If final: produce per-column sums over the 64 rows instead of writing `out`.
// ---------------------------------------------------------------------------
__device__ __forceinline__ void do_layer(
    const float* __restrict__ in, const float* __restrict__ W, const float* __restrict__ bias,
    int K, float* out, bool final_,
    float* whi0, float* wlo0, float* whi1, float* wlo1,
    float* redscratch /*>= 2048 floats*/, float* colsum /*256 floats*/,
    int block)
{
    const int tid  = threadIdx.x;
    const int lane = tid & 31;
    const int wp   = tid >> 5;     // warp id: covers cols [wp*32, wp*32+32)
    const int g    = lane >> 2;    // group id 0..7
    const int t    = lane & 3;     // thread-in-group 0..3

    float c[4][4][4];              // [row-block 0..3][n-tile 0..3][frag]
#pragma unroll
    for (int rb = 0; rb < 4; rb++)
#pragma unroll
        for (int nt = 0; nt < 4; nt++)
#pragma unroll
            for (int i = 0; i < 4; i++) c[rb][nt][i] = 0.f;

    const int nk = K >> 3;

    // prologue: stage slice 0
    {
        float4 v[2];
        stage_load(W, 0, v, tid);
        stage_store(v, whi0, wlo0, tid);
    }
    __syncthreads();

    for (int ks = 0; ks < nk; ks++) {
        float* whi = (ks & 1) ? whi1 : whi0;
        float* wlo = (ks & 1) ? wlo1 : wlo0;
        const bool more = (ks + 1 < nk);
        float4 nv[2];
        if (more) stage_load(W, (ks + 1) * 8, nv, tid);

        const int kk = ks * 8;

        // A fragments (shared across all n-tiles); rows = rb*16 + {g, g+8}
        uint32_t a[4][4];
#pragma unroll
        for (int rb = 0; rb < 4; rb++) {
            const int r = rb * 16 + g;
            a[rb][0] = __float_as_uint(in[r * ASTRIDE + kk + t]);
            a[rb][1] = __float_as_uint(in[(r + 8) * ASTRIDE + kk + t]);
            a[rb][2] = __float_as_uint(in[r * ASTRIDE + kk + t + 4]);
            a[rb][3] = __float_as_uint(in[(r + 8) * ASTRIDE + kk + t + 4]);
        }

#pragma unroll
        for (int nt = 0; nt < 4; nt++) {
            const int col = wp * 32 + nt * 8 + g;
            const uint32_t bh0 = __float_as_uint(whi[t * WSTRIDE + col]);
            const uint32_t bh1 = __float_as_uint(whi[(t + 4) * WSTRIDE + col]);
            const uint32_t bl0 = __float_as_uint(wlo[t * WSTRIDE + col]);
            const uint32_t bl1 = __float_as_uint(wlo[(t + 4) * WSTRIDE + col]);
#pragma unroll
            for (int rb = 0; rb < 4; rb++) {
                mma8(c[rb][nt], a[rb], bh0, bh1);
                mma8(c[rb][nt], a[rb], bl0, bl1);
            }
        }

        if (more) {
            float* nwhi = (ks & 1) ? whi0 : whi1;
            float* nwlo = (ks & 1) ? wlo0 : wlo1;
            stage_store(nv, nwhi, nwlo, tid);
        }
        __syncthreads();
    }

    // epilogue
    if (!final_) {
#pragma unroll
        for (int rb = 0; rb < 4; rb++) {
            const int r = rb * 16 + g;
#pragma unroll
            for (int nt = 0; nt < 4; nt++) {
                const int col = wp * 32 + nt * 8 + 2 * t;
                const float bb0 = bias[col], bb1 = bias[col + 1];
                out[r * ASTRIDE + col]           = tf32r(fmaxf(c[rb][nt][0] + bb0, 0.f));
                out[r * ASTRIDE + col + 1]       = tf32r(fmaxf(c[rb][nt][1] + bb1, 0.f));
                out[(r + 8) * ASTRIDE + col]     = tf32r(fmaxf(c[rb][nt][2] + bb0, 0.f));
                out[(r + 8) * ASTRIDE + col + 1] = tf32r(fmaxf(c[rb][nt][3] + bb1, 0.f));
            }
        }
        __syncthreads();
    } else {
        // Deterministic per-column reduction over this CTA's 64 rows.
        // Each (col) has exactly 8 contributing lanes (g = 0..7); thread reduces its 8 rows first.
#pragma unroll
        for (int nt = 0; nt < 4; nt++) {
            const int col = wp * 32 + nt * 8 + 2 * t;
            const float bb0 = bias[col], bb1 = bias[col + 1];
            float s0 = 0.f, s1 = 0.f;
#pragma unroll
            for (int rb = 0; rb < 4; rb++) {
                s0 += fmaxf(c[rb][nt][0] + bb0, 0.f) + fmaxf(c[rb][nt][2] + bb0, 0.f);
                s1 += fmaxf(c[rb][nt][1] + bb1, 0.f) + fmaxf(c[rb][nt][3] + bb1, 0.f);
            }
            redscratch[col * 8 + g]       = s0;
            redscratch[(col + 1) * 8 + g] = s1;
        }
        __syncthreads();
        float s = 0.f;
#pragma unroll
        for (int i = 0; i < 8; i++) s += redscratch[tid * 8 + i];
        colsum[tid] = s;
        __syncthreads();
        g_partial[block * NHID + tid] = colsum[tid];
    }
}

// ---------------------------------------------------------------------------
// Encoder: 3 fused layers per 64-row tile, per-tile column sums out to g_partial
// ---------------------------------------------------------------------------
__global__ void __launch_bounds__(NTHREADS, 1)
encoder_kernel(const float* __restrict__ x,
               const float* __restrict__ W1, const float* __restrict__ b1,
               const float* __restrict__ W2, const float* __restrict__ b2,
               const float* __restrict__ W3, const float* __restrict__ b3)
{
    extern __shared__ float smem[];
    float* bufA   = smem;                         // 64 x 260
    float* bufB   = bufA + TM * ASTRIDE;          // 64 x 260
    float* whi0   = bufB + TM * ASTRIDE;          // 8 x 264
    float* wlo0   = whi0 + 8 * WSTRIDE;
    float* whi1   = wlo0 + 8 * WSTRIDE;
    float* wlo1   = whi1 + 8 * WSTRIDE;
    float* colsum = wlo1 + 8 * WSTRIDE;           // 256

    const int tid   = threadIdx.x;
    const int block = blockIdx.x;
    const int row0  = block * TM;

    // Stage x tile [64 x 128] into bufA (tf32-rounded), coalesced float4 loads
    const float4* xt = reinterpret_cast<const float4*>(x + (size_t)row0 * NIN);
#pragma unroll
    for (int i = tid; i < TM * NIN / 4; i += NTHREADS) {
        float4 v = xt[i];
        int lin = i * 4;
        int r   = lin >> 7;     // / 128
        int cc  = lin & 127;
        float* p = bufA + r * ASTRIDE + cc;
        p[0] = tf32r(v.x); p[1] = tf32r(v.y); p[2] = tf32r(v.z); p[3] = tf32r(v.w);
    }
    __syncthreads();

    do_layer(bufA, W1, b1, NIN,  bufB, false, whi0, wlo0, whi1, wlo1, bufB, colsum, block);
    do_layer(bufB, W2, b2, NHID, bufA, false, whi0, wlo0, whi1, wlo1, bufA, colsum, block);
    // final layer: input bufA, use bufB as the (now free) reduction scratch
    do_layer(bufA, W3, b3, NHID, nullptr, true, whi0, wlo0, whi1, wlo1, bufB, colsum, block);
}

// ---------------------------------------------------------------------------
// Decoder: reduce partials -> m, p = relu(m*m), 3 fp32 linear layers. 1 CTA / batch.
// ---------------------------------------------------------------------------
__global__ void __launch_bounds__(256, 1)
decoder_kernel(const float* __restrict__ D1, const float* __restrict__ c1,
               const float* __restrict__ D2, const float* __restrict__ c2,
               const float* __restrict__ D3, const float* __restrict__ c3,
               float* __restrict__ out)
{
    __shared__ float p[NHID];
    __shared__ float d1s[NDEC];
    __shared__ float d2s[NDEC];
    const int b   = blockIdx.x;
    const int tid = threadIdx.x;

    // deterministic reduction over the 64 tile-partials of this batch
    const int tiles_per_batch = NSET / TM;  // 64
    float s = 0.f;
    const float* base = g_partial + (size_t)(b * tiles_per_batch) * NHID + tid;
#pragma unroll 8
    for (int i = 0; i < tiles_per_batch; i++) s += base[(size_t)i * NHID];
    const float m = s * (1.0f / NSET);
    p[tid] = fmaxf(m * m, 0.f);
    __syncthreads();

    // d1 = relu(p @ D1 + c1)   [256 -> 512]
    for (int j = tid; j < NDEC; j += 256) {
        float a0 = 0.f, a1 = 0.f, a2 = 0.f, a3 = 0.f;
#pragma unroll 4
        for (int k = 0; k < NHID; k += 4) {
            a0 += p[k]     * D1[(k)     * NDEC + j];
            a1 += p[k + 1] * D1[(k + 1) * NDEC + j];
            a2 += p[k + 2] * D1[(k + 2) * NDEC + j];
            a3 += p[k + 3] * D1[(k + 3) * NDEC + j];
        }
        d1s[j] = fmaxf(c1[j] + ((a0 + a1) + (a2 + a3)), 0.f);
    }
    __syncthreads();

    // d2 = relu(d1 @ D2 + c2)  [512 -> 512]
    for (int j = tid; j < NDEC; j += 256) {
        float a0 = 0.f, a1 = 0.f, a2 = 0.f, a3 = 0.f;
#pragma unroll 4
        for (int k = 0; k < NDEC; k += 4) {
            a0 += d1s[k]     * D2[(k)     * NDEC + j];
            a1 += d1s[k + 1] * D2[(k + 1) * NDEC + j];
            a2 += d1s[k + 2] * D2[(k + 2) * NDEC + j];
            a3 += d1s[k + 3] * D2[(k + 3) * NDEC + j];
        }
        d2s[j] = fmaxf(c2[j] + ((a0 + a1) + (a2 + a3)), 0.f);
    }
    __syncthreads();

    // out = d2 @ D3 + c3       [512 -> 10]
    if (tid < NOUT) {
        float a0 = 0.f, a1 = 0.f;
#pragma unroll 8
        for (int k = 0; k < NDEC; k += 2) {
            a0 += d2s[k]     * D3[(k)     * NOUT + tid];
            a1 += d2s[k + 1] * D3[(k + 1) * NOUT + tid];
        }
        out[b * NOUT + tid] = c3[tid] + (a0 + a1);
    }
}

// ---------------------------------------------------------------------------
extern "C" void kernel_launch(void* const* d_in, const int* in_sizes, int n_in,
                              void* d_out, int out_size)
{
    (void)in_sizes; (void)n_in; (void)out_size;
    const float* x  = (const float*)d_in[0];
    const float* W1 = (const float*)d_in[1];
    const float* b1 = (const float*)d_in[2];
    const float* W2 = (const float*)d_in[3];
    const float* b2 = (const float*)d_in[4];
    const float* W3 = (const float*)d_in[5];
    const float* b3 = (const float*)d_in[6];
    const float* D1 = (const float*)d_in[7];
    const float* c1 = (const float*)d_in[8];
    const float* D2 = (const float*)d_in[9];
    const float* c2 = (const float*)d_in[10];
    const float* D3 = (const float*)d_in[11];
    const float* c3 = (const float*)d_in[12];

    const int smem_bytes = (2 * TM * ASTRIDE + 4 * 8 * WSTRIDE + 256) * (int)sizeof(float);
    cudaFuncSetAttribute(encoder_kernel, cudaFuncAttributeMaxDynamicSharedMemorySize, smem_bytes);

    encoder_kernel<<<NTILES_ENC, NTHREADS, smem_bytes>>>(x, W1, b1, W2, b2, W3, b3);
    decoder_kernel<<<BATCH, 256>>>(D1, c1, D2, c2, D3, c3, (float*)d_out);
}